// round 8
// baseline (speedup 1.0000x reference)
#include <cuda_runtime.h>
#include <math.h>

#define BB   16
#define NN   96
#define HH   256
#define BINC 11

// Scratch (__device__ globals: no allocation).
__device__ float g_yb [BB * NN * HH];   // y + b_bin   (base rows, 1.5 MB)
__device__ float g_yT [BB * HH * NN];   // y transposed [b][k][j] (1.5 MB)

// ---- packed f32x2 helpers (u64 carrier, "l" constraints) ------------------
typedef unsigned long long f2;
__device__ __forceinline__ f2 pk(float lo, float hi) {
    f2 r; asm("mov.b64 %0, {%1,%2};" : "=l"(r) : "f"(lo), "f"(hi)); return r;
}
__device__ __forceinline__ void upk(f2 v, float& lo, float& hi) {
    asm("mov.b64 {%0,%1}, %2;" : "=f"(lo), "=f"(hi) : "l"(v));
}
__device__ __forceinline__ f2 fma2(f2 a, f2 b, f2 c) {
    f2 d; asm("fma.rn.f32x2 %0, %1, %2, %3;" : "=l"(d) : "l"(a), "l"(b), "l"(c)); return d;
}
__device__ __forceinline__ f2 add2(f2 a, f2 b) {
    f2 d; asm("add.rn.f32x2 %0, %1, %2;" : "=l"(d) : "l"(a), "l"(b)); return d;
}

// ---------------------------------------------------------------------------
// Kernel 1: y = x @ W_atom. Block = 8 rows, 1024 threads = 256 k x 4 h-quarters.
// W loads software-pipelined (prefetch next iteration -> MLP 8).
// Writes g_yb = y + b_bin (coalesced) and g_yT (transposed).
// ---------------------------------------------------------------------------
#define PR 8
__global__ __launch_bounds__(1024) void proj_kernel(const float* __restrict__ x,
                                                    const float* __restrict__ W,
                                                    const float* __restrict__ b_bin) {
    __shared__ float xs[PR * HH];              // 8 KB
    __shared__ float part[3][PR * HH];         // 24 KB (quarters 1..3)
    const int r0  = blockIdx.x * PR;           // 8 rows, same batch (96 % 8 == 0)
    const int tid = threadIdx.x;
    const int k   = tid & 255;
    const int q   = tid >> 8;                  // h-quarter 0..3
    const int b   = r0 / NN;
    const int jl  = r0 % NN;

    for (int idx = tid; idx < PR * HH; idx += 1024) xs[idx] = x[r0 * HH + idx];
    __syncthreads();

    f2 acc[PR];
#pragma unroll
    for (int r = 0; r < PR; ++r) acc[r] = 0ull;

    const ulonglong2* xs2 = (const ulonglong2*)xs;   // [r*64 + h4]
    const int h4base = q * 16;

    // software pipeline over 16 h4 iterations
    const float* Wp = W + (h4base * 4) * HH + k;
    float w0 = __ldg(Wp + 0 * HH), w1 = __ldg(Wp + 1 * HH);
    float w2 = __ldg(Wp + 2 * HH), w3 = __ldg(Wp + 3 * HH);

#pragma unroll 4
    for (int h4i = 0; h4i < 16; ++h4i) {
        const int h4 = h4base + h4i;
        f2 wa = pk(w0, w1), wbq = pk(w2, w3);
        // prefetch next iteration's W (dead regs)
        if (h4i < 15) {
            const float* Wn = Wp + 4 * HH;
            w0 = __ldg(Wn + 0 * HH); w1 = __ldg(Wn + 1 * HH);
            w2 = __ldg(Wn + 2 * HH); w3 = __ldg(Wn + 3 * HH);
            Wp = Wn;
        }
#pragma unroll
        for (int r = 0; r < PR; ++r) {
            ulonglong2 xv = xs2[r * 64 + h4];
            acc[r] = fma2(xv.x, wa, acc[r]);
            acc[r] = fma2(xv.y, wbq, acc[r]);
        }
    }
    if (q > 0) {
#pragma unroll
        for (int r = 0; r < PR; ++r) {
            float lo, hi; upk(acc[r], lo, hi);
            part[q - 1][r * HH + k] = lo + hi;
        }
    }
    __syncthreads();
    if (q == 0) {
        const float bbk = __ldg(&b_bin[k]);
#pragma unroll
        for (int r = 0; r < PR; ++r) {
            float lo, hi; upk(acc[r], lo, hi);
            const float v = lo + hi + part[0][r * HH + k]
                          + part[1][r * HH + k] + part[2][r * HH + k];
            g_yb[(r0 + r) * HH + k]          = v + bbk;
            g_yT[(b * HH + k) * NN + jl + r] = v;
        }
    }
}

// ---------------------------------------------------------------------------
// Kernel 2: fused scores + pair writes + context.
// Block = (b, 4 i). 384 threads.
// Phase A: 12 warps = 4 i x 3 j-groups; thread owns one (i,j), loops k.
//          No cross-lane reduction. Sigmoid inline -> att_s[4][96].
// Phase B: thread = (j-phase 0..5, k-quad 0..63); for each of the 4 i's,
//          stream pair[i,j,:] = x_i + x_j (__stcs) + fused ctx partials.
//          x[b] (96 KB) stays L1-resident across the 4 i's.
// ---------------------------------------------------------------------------
__global__ __launch_bounds__(384, 2) void score_write_kernel(
    const float* __restrict__ x,
    const float* __restrict__ bin,
    const float* __restrict__ W_bin,
    const float* __restrict__ w_score,
    const float* __restrict__ b_score,
    float* __restrict__ ctx_out,
    float* __restrict__ pair_out)
{
    __shared__ float Wb_s[BINC * HH];      // 11 KB
    __shared__ float ws_s[HH];             // 1 KB
    __shared__ float yb_s[4 * HH];         // 4 KB  (base rows for the 4 i's)
    __shared__ float sbin[4 * NN * BINC];  // 16.5 KB
    __shared__ float att_s[4][NN];         // 1.5 KB
    __shared__ float cpart[6][HH];         // 6 KB

    const int blk = blockIdx.x;            // 0..383
    const int b   = blk / (NN / 4);
    const int i0  = (blk % (NN / 4)) * 4;
    const int tid = threadIdx.x;

    // ---- stage operands (coalesced) ----
    for (int idx = tid; idx < BINC * HH; idx += 384) Wb_s[idx] = W_bin[idx];
    for (int idx = tid; idx < HH; idx += 384)        ws_s[idx] = w_score[idx];
    for (int idx = tid; idx < 4 * HH; idx += 384)
        yb_s[idx] = g_yb[(b * NN + i0) * HH + idx];
    {
        const float* src = bin + (size_t)(b * NN + i0) * NN * BINC;
        for (int idx = tid; idx < 4 * NN * BINC; idx += 384) sbin[idx] = src[idx];
    }
    __syncthreads();

    // ================= Phase A: scores =================
    {
        const int w  = tid >> 5;
        const int L  = tid & 31;
        const int iw = w & 3;                // i within block
        const int jg = w >> 2;               // j-group 0..2
        const int j  = jg * 32 + L;

        f2 bc2[BINC];
#pragma unroll
        for (int c = 0; c < BINC; ++c) {
            const float v = sbin[(iw * NN + j) * BINC + c];
            bc2[c] = pk(v, v);
        }

        const float* yTp = g_yT + (size_t)b * HH * NN + j;   // [k]: +k*NN
        const ulonglong2* wbp = (const ulonglong2*)Wb_s;     // [c*64 + k4]
        const ulonglong2* bsp = (const ulonglong2*)(yb_s + iw * HH);
        const ulonglong2* wsp = (const ulonglong2*)ws_s;

        // prefetch first yT quad
        float y0 = yTp[0 * NN], y1 = yTp[1 * NN], y2 = yTp[2 * NN], y3 = yTp[3 * NN];

        f2 acc2 = 0ull;
        for (int k4 = 0; k4 < HH / 4; ++k4) {
            ulonglong2 bs = bsp[k4];
            f2 h01 = add2(bs.x, pk(y0, y1));
            f2 h23 = add2(bs.y, pk(y2, y3));

            // prefetch next quad of y_j (regs dead)
            if (k4 < HH / 4 - 1) {
                const float* yn = yTp + (k4 * 4 + 4) * NN;
                y0 = yn[0 * NN]; y1 = yn[1 * NN];
                y2 = yn[2 * NN]; y3 = yn[3 * NN];
            }

#pragma unroll
            for (int c = 0; c < BINC; ++c) {
                ulonglong2 wv = wbp[c * 64 + k4];
                h01 = fma2(bc2[c], wv.x, h01);
                h23 = fma2(bc2[c], wv.y, h23);
            }

            float a0, a1, a2, a3;
            upk(h01, a0, a1); upk(h23, a2, a3);
            a0 = fmaxf(a0, 0.f); a1 = fmaxf(a1, 0.f);
            a2 = fmaxf(a2, 0.f); a3 = fmaxf(a3, 0.f);

            ulonglong2 wsv = wsp[k4];
            acc2 = fma2(pk(a0, a1), wsv.x, acc2);
            acc2 = fma2(pk(a2, a3), wsv.y, acc2);
        }

        float sl, sh; upk(acc2, sl, sh);
        const float s = sl + sh + __ldg(b_score);
        att_s[iw][j] = 1.f / (1.f + __expf(-s));
    }
    __syncthreads();

    // ================= Phase B: pair writes + context =================
    {
        const int tq = tid & 63;             // k-quad 0..63
        const int ph = tid >> 6;             // j-phase 0..5
        const float4* x4 = (const float4*)(x + (size_t)b * NN * HH);

#pragma unroll
        for (int ii = 0; ii < 4; ++ii) {
            const int gi = b * NN + i0 + ii;
            const float4 xi4 = x4[(i0 + ii) * 64 + tq];
            float4* po = (float4*)(pair_out + (size_t)gi * NN * HH);

            float c0 = 0.f, c1 = 0.f, c2 = 0.f, c3 = 0.f;
#pragma unroll 4
            for (int jj = 0; jj < NN / 6; ++jj) {
                const int j = ph + 6 * jj;
                const float4 xj = x4[j * 64 + tq];      // L1-resident after ii=0
                const float  a  = att_s[ii][j];
                __stcs(&po[j * 64 + tq],
                       make_float4(xi4.x + xj.x, xi4.y + xj.y,
                                   xi4.z + xj.z, xi4.w + xj.w));
                c0 = fmaf(a, xj.x, c0); c1 = fmaf(a, xj.y, c1);
                c2 = fmaf(a, xj.z, c2); c3 = fmaf(a, xj.w, c3);
            }
            ((float4*)cpart[ph])[tq] = make_float4(c0, c1, c2, c3);
            __syncthreads();
            if (tid < HH) {
                ctx_out[(size_t)gi * HH + tid] =
                    cpart[0][tid] + cpart[1][tid] + cpart[2][tid] +
                    cpart[3][tid] + cpart[4][tid] + cpart[5][tid];
            }
            __syncthreads();
        }
    }
}

// ---------------------------------------------------------------------------
extern "C" void kernel_launch(void* const* d_in, const int* in_sizes, int n_in,
                              void* d_out, int out_size) {
    const float* x       = (const float*)d_in[0];
    const float* bin     = (const float*)d_in[1];
    const float* W_atom  = (const float*)d_in[2];
    const float* W_bin   = (const float*)d_in[3];
    const float* b_bin   = (const float*)d_in[4];
    const float* w_score = (const float*)d_in[5];
    const float* b_score = (const float*)d_in[6];

    float* out  = (float*)d_out;
    float* ctx  = out;                            // context: B*N*H
    float* pair = out + (size_t)BB * NN * HH;     // atom_pair: B*N*N*H

    proj_kernel<<<BB * NN / PR, 1024>>>(x, W_atom, b_bin);
    score_write_kernel<<<BB * NN / 4, 384>>>(x, bin, W_bin, w_score, b_score,
                                             ctx, pair);
}